// round 4
// baseline (speedup 1.0000x reference)
#include <cuda_runtime.h>
#include <math.h>

#define NBK  5
#define HD   32
#define DIN  4
#define TT   25
#define HIDD 64
#define TPB  64           // threads per CTA (3 CTAs/SM -> 12 warps)
#define SPT  2            // samples per thread
#define SPC  (TPB*SPT)    // 128 samples per CTA
#define TILES 256         // 32768 / 128
#define GRID (TILES*NBK)  // 1280
#define JB   4            // j-block per pass
#define NPASS (HD/JB)     // 8

typedef unsigned long long u64;

// Weights interleaved [k][j][(i,f,g,o)] -> one LDS.128 = 4 gate weights of (k,j),
// reused by both samples: 16B per 8 FMAs.
struct SmemLayout {
    float Wp0p[DIN][HD][4];   //  2048 B
    float Wh0p[HD][HD][4];    // 16384 B
    float Wp1p[HD][HD][4];    // 16384 B
    float Wh1p[HD][HD][4];    // 16384 B
    float bp0[HD][4];         //   512 B
    float bp1[HD][4];         //   512 B
    float2 h1s[HD][TPB];      // 16384 B  (layer-1 h state, packed (a,b))
};                            // 68608 B -> 3 CTAs/SM

// MLP-weight overlay offsets (floats) into the weights region after recurrence:
#define OV_W1 0
#define OV_B1 2048
#define OV_W2 2112
#define OV_B2 6208

// c-state scratch in L2 (per CTA: 2 layers x 32 j x TPB tid, packed (a,b))
__device__ float2 g_cst[GRID][2][HD][TPB];

__device__ __forceinline__ u64 pk2(float v) {
    u64 r; asm("mov.b64 %0, {%1, %1};" : "=l"(r) : "f"(v)); return r;
}
__device__ __forceinline__ u64 f2fma(u64 a, u64 b, u64 c) {
    u64 d; asm("fma.rn.f32x2 %0, %1, %2, %3;" : "=l"(d) : "l"(a), "l"(b), "l"(c));
    return d;
}
__device__ __forceinline__ void unpk(u64 v, float& lo, float& hi) {
    asm("mov.b64 {%0, %1}, %2;" : "=f"(lo), "=f"(hi) : "l"(v));
}
__device__ __forceinline__ float sigf(float v) {
    return __fdividef(1.0f, 1.0f + __expf(-v));
}
__device__ __forceinline__ float tanhr(float v) {
    return __fdividef(2.0f, 1.0f + __expf(-2.0f * v)) - 1.0f;
}

__global__ void __launch_bounds__(TPB, 3) lstm_fused(
    const float* __restrict__ x,    const float* __restrict__ mask,
    const float* __restrict__ Wih0, const float* __restrict__ Whh0,
    const float* __restrict__ bih0, const float* __restrict__ bhh0,
    const float* __restrict__ Wih1, const float* __restrict__ Whh1,
    const float* __restrict__ bih1, const float* __restrict__ bhh1,
    const float* __restrict__ W1,   const float* __restrict__ b1,
    const float* __restrict__ W2,   const float* __restrict__ b2,
    float* __restrict__ out)
{
    extern __shared__ float smraw[];
    SmemLayout* S = reinterpret_cast<SmemLayout*>(smraw);
    const int tid  = threadIdx.x;
    const int ib   = 4 - (blockIdx.x >> 8);       // heavy blocks launch first
    const int tile = blockIdx.x & (TILES - 1);
    const int bA   = tile * SPC + tid;            // sample A
    const int bB   = bA + TPB;                    // sample B

    float2* gc0 = &g_cst[blockIdx.x][0][0][0];
    float2* gc1 = &g_cst[blockIdx.x][1][0][0];

    // ---- stage weights into SMEM (interleaved) ----
    {
        const float* wih0 = Wih0 + ib * 4 * HD * DIN;
        for (int idx = tid; idx < 4 * HD * DIN; idx += TPB) {
            int r = idx / DIN, k = idx % DIN, g = r >> 5, j = r & 31;
            S->Wp0p[k][j][g] = wih0[idx];
        }
        const float* whh0 = Whh0 + ib * 4 * HD * HD;
        const float* wih1 = Wih1 + ib * 4 * HD * HD;
        const float* whh1 = Whh1 + ib * 4 * HD * HD;
        for (int idx = tid; idx < 4 * HD * HD; idx += TPB) {
            int r = idx / HD, k = idx % HD, g = r >> 5, j = r & 31;
            S->Wh0p[k][j][g] = whh0[idx];
            S->Wp1p[k][j][g] = wih1[idx];
            S->Wh1p[k][j][g] = whh1[idx];
        }
        for (int idx = tid; idx < 4 * HD; idx += TPB) {
            int g = idx >> 5, j = idx & 31;
            S->bp0[j][g] = bih0[ib * 4 * HD + idx] + bhh0[ib * 4 * HD + idx];
            S->bp1[j][g] = bih1[ib * 4 * HD + idx] + bhh1[ib * 4 * HD + idx];
        }
    }
#pragma unroll
    for (int j = 0; j < HD; j++) S->h1s[j][tid] = make_float2(0.0f, 0.0f);
    __syncthreads();

    // ---- register state ----
    float h0a[HD], h0b[HD], na[HD], nb[HD];
#pragma unroll
    for (int j = 0; j < HD; j++) { h0a[j] = 0.0f; h0b[j] = 0.0f; }

    const int Ti = 5 * (ib + 1);
    const float4* xpa = reinterpret_cast<const float4*>(x)    + (size_t)bA * TT + (TT - Ti);
    const float4* mpa = reinterpret_cast<const float4*>(mask) + (size_t)bA * TT + (TT - Ti);
    const float4* xpb = reinterpret_cast<const float4*>(x)    + (size_t)bB * TT + (TT - Ti);
    const float4* mpb = reinterpret_cast<const float4*>(mask) + (size_t)bB * TT + (TT - Ti);
    float4 xva = __ldg(xpa), mva = __ldg(mpa);
    float4 xvb = __ldg(xpb), mvb = __ldg(mpb);

    for (int s = 0; s < Ti; s++) {
        u64 xma2[DIN], xmb2[DIN];
        xma2[0] = pk2(xva.x * mva.x); xma2[1] = pk2(xva.y * mva.y);
        xma2[2] = pk2(xva.z * mva.z); xma2[3] = pk2(xva.w * mva.w);
        xmb2[0] = pk2(xvb.x * mvb.x); xmb2[1] = pk2(xvb.y * mvb.y);
        xmb2[2] = pk2(xvb.z * mvb.z); xmb2[3] = pk2(xvb.w * mvb.w);
        if (s + 1 < Ti) {
            xva = __ldg(xpa + s + 1); mva = __ldg(mpa + s + 1);
            xvb = __ldg(xpb + s + 1); mvb = __ldg(mpb + s + 1);
        }

        // ================= layer 0 =================
#pragma unroll
        for (int p = 0; p < NPASS; p++) {
            u64 iA[JB], gA[JB], iB[JB], gB[JB];
            float2 cp[JB];
#pragma unroll
            for (int q = 0; q < JB; q++) {
                const int j = p * JB + q;
                ulonglong2 bb = *reinterpret_cast<const ulonglong2*>(S->bp0[j]);
                iA[q] = bb.x; gA[q] = bb.y; iB[q] = bb.x; gB[q] = bb.y;
                cp[q] = (s == 0) ? make_float2(0.0f, 0.0f) : gc0[j * TPB + tid];
            }
#pragma unroll
            for (int k = 0; k < DIN; k++) {
#pragma unroll
                for (int q = 0; q < JB; q++) {
                    ulonglong2 w = *reinterpret_cast<const ulonglong2*>(S->Wp0p[k][p * JB + q]);
                    iA[q] = f2fma(w.x, xma2[k], iA[q]); gA[q] = f2fma(w.y, xma2[k], gA[q]);
                    iB[q] = f2fma(w.x, xmb2[k], iB[q]); gB[q] = f2fma(w.y, xmb2[k], gB[q]);
                }
            }
#pragma unroll
            for (int k = 0; k < HD; k++) {
                u64 ha = pk2(h0a[k]), hb = pk2(h0b[k]);
#pragma unroll
                for (int q = 0; q < JB; q++) {
                    ulonglong2 w = *reinterpret_cast<const ulonglong2*>(S->Wh0p[k][p * JB + q]);
                    iA[q] = f2fma(w.x, ha, iA[q]); gA[q] = f2fma(w.y, ha, gA[q]);
                    iB[q] = f2fma(w.x, hb, iB[q]); gB[q] = f2fma(w.y, hb, gB[q]);
                }
            }
#pragma unroll
            for (int q = 0; q < JB; q++) {
                const int j = p * JB + q;
                float ai, af, ag, ao, bi, bf, bg, bo;
                unpk(iA[q], ai, af); unpk(gA[q], ag, ao);
                unpk(iB[q], bi, bf); unpk(gB[q], bg, bo);
                float ca = sigf(af) * cp[q].x + sigf(ai) * tanhr(ag);
                float cb = sigf(bf) * cp[q].y + sigf(bi) * tanhr(bg);
                gc0[j * TPB + tid] = make_float2(ca, cb);
                na[j] = sigf(ao) * tanhr(ca);
                nb[j] = sigf(bo) * tanhr(cb);
            }
        }
#pragma unroll
        for (int j = 0; j < HD; j++) { h0a[j] = na[j]; h0b[j] = nb[j]; }

        // ================= layer 1 =================
#pragma unroll
        for (int p = 0; p < NPASS; p++) {
            u64 iA[JB], gA[JB], iB[JB], gB[JB];
            float2 cp[JB];
#pragma unroll
            for (int q = 0; q < JB; q++) {
                const int j = p * JB + q;
                ulonglong2 bb = *reinterpret_cast<const ulonglong2*>(S->bp1[j]);
                iA[q] = bb.x; gA[q] = bb.y; iB[q] = bb.x; gB[q] = bb.y;
                cp[q] = (s == 0) ? make_float2(0.0f, 0.0f) : gc1[j * TPB + tid];
            }
#pragma unroll
            for (int k = 0; k < HD; k++) {           // input = new h0 (regs)
                u64 ha = pk2(h0a[k]), hb = pk2(h0b[k]);
#pragma unroll
                for (int q = 0; q < JB; q++) {
                    ulonglong2 w = *reinterpret_cast<const ulonglong2*>(S->Wp1p[k][p * JB + q]);
                    iA[q] = f2fma(w.x, ha, iA[q]); gA[q] = f2fma(w.y, ha, gA[q]);
                    iB[q] = f2fma(w.x, hb, iB[q]); gB[q] = f2fma(w.y, hb, gB[q]);
                }
            }
#pragma unroll
            for (int k = 0; k < HD; k++) {           // recurrent = h1 (smem)
                float2 hv = S->h1s[k][tid];
                u64 ha = pk2(hv.x), hb = pk2(hv.y);
#pragma unroll
                for (int q = 0; q < JB; q++) {
                    ulonglong2 w = *reinterpret_cast<const ulonglong2*>(S->Wh1p[k][p * JB + q]);
                    iA[q] = f2fma(w.x, ha, iA[q]); gA[q] = f2fma(w.y, ha, gA[q]);
                    iB[q] = f2fma(w.x, hb, iB[q]); gB[q] = f2fma(w.y, hb, gB[q]);
                }
            }
#pragma unroll
            for (int q = 0; q < JB; q++) {
                const int j = p * JB + q;
                float ai, af, ag, ao, bi, bf, bg, bo;
                unpk(iA[q], ai, af); unpk(gA[q], ag, ao);
                unpk(iB[q], bi, bf); unpk(gB[q], bg, bo);
                float ca = sigf(af) * cp[q].x + sigf(ai) * tanhr(ag);
                float cb = sigf(bf) * cp[q].y + sigf(bi) * tanhr(bg);
                gc1[j * TPB + tid] = make_float2(ca, cb);
                na[j] = sigf(ao) * tanhr(ca);         // na/nb now hold new h1
                nb[j] = sigf(bo) * tanhr(cb);
            }
        }
#pragma unroll
        for (int j = 0; j < HD; j++) S->h1s[j][tid] = make_float2(na[j], nb[j]);
    }

    // ---- MLP head: stage W1/W2 into dead gate-weight smem ----
    __syncthreads();
    float* ov = smraw;   // overlay at base of weights region
    for (int idx = tid; idx < HIDD * HD; idx += TPB)   ov[OV_W1 + idx] = W1[idx];
    for (int idx = tid; idx < HIDD * HIDD; idx += TPB) {
        int n = idx / HIDD, m = idx % HIDD;
        ov[OV_W2 + m * HIDD + n] = W2[idx];            // transposed [m][n]
    }
    if (tid < HIDD) { ov[OV_B1 + tid] = b1[tid]; ov[OV_B2 + tid] = b2[tid]; }
    __syncthreads();

    // na/nb hold final h1 for samples A/B
#pragma unroll
    for (int smp = 0; smp < 2; smp++) {
        const float* hr = (smp == 0) ? na : nb;
        float acc2[HIDD];
#pragma unroll
        for (int n = 0; n < HIDD; n++) acc2[n] = ov[OV_B2 + n];
        for (int m = 0; m < HIDD; m++) {
            float tm = ov[OV_B1 + m];
            const float4* w1r = reinterpret_cast<const float4*>(&ov[OV_W1 + m * HD]);
#pragma unroll
            for (int q = 0; q < HD / 4; q++) {
                float4 w = w1r[q];
                tm += hr[4 * q + 0] * w.x + hr[4 * q + 1] * w.y
                    + hr[4 * q + 2] * w.z + hr[4 * q + 3] * w.w;
            }
            tm = 0.5f * tm * (1.0f + erff(tm * 0.70710678118654752f));
            const float4* w2r = reinterpret_cast<const float4*>(&ov[OV_W2 + m * HIDD]);
#pragma unroll
            for (int q = 0; q < HIDD / 4; q++) {
                float4 w = w2r[q];
                acc2[4 * q + 0] += tm * w.x; acc2[4 * q + 1] += tm * w.y;
                acc2[4 * q + 2] += tm * w.z; acc2[4 * q + 3] += tm * w.w;
            }
        }
        const int b = (smp == 0) ? bA : bB;
        float4* op = reinterpret_cast<float4*>(out + ((size_t)b * NBK + ib) * HIDD);
#pragma unroll
        for (int q = 0; q < HIDD / 4; q++)
            op[q] = make_float4(acc2[4 * q], acc2[4 * q + 1],
                                acc2[4 * q + 2], acc2[4 * q + 3]);
    }
}

extern "C" void kernel_launch(void* const* d_in, const int* in_sizes, int n_in,
                              void* d_out, int out_size)
{
    const float* x    = (const float*)d_in[0];
    const float* mask = (const float*)d_in[1];
    const float* Wih0 = (const float*)d_in[2];
    const float* Whh0 = (const float*)d_in[3];
    const float* bih0 = (const float*)d_in[4];
    const float* bhh0 = (const float*)d_in[5];
    const float* Wih1 = (const float*)d_in[6];
    const float* Whh1 = (const float*)d_in[7];
    const float* bih1 = (const float*)d_in[8];
    const float* bhh1 = (const float*)d_in[9];
    const float* W1   = (const float*)d_in[10];
    const float* b1   = (const float*)d_in[11];
    const float* W2   = (const float*)d_in[12];
    const float* b2   = (const float*)d_in[13];
    float* out = (float*)d_out;

    const size_t smem = sizeof(SmemLayout);   // 68608 B -> 3 CTAs/SM
    cudaFuncSetAttribute(lstm_fused, cudaFuncAttributeMaxDynamicSharedMemorySize,
                         (int)smem);
    lstm_fused<<<GRID, TPB, smem>>>(x, mask, Wih0, Whh0, bih0, bhh0,
                                    Wih1, Whh1, bih1, bhh1, W1, b1, W2, b2, out);
}

// round 5
// speedup vs baseline: 2.9388x; 2.9388x over previous
#include <cuda_runtime.h>
#include <math.h>

#define NBK  5
#define HD   32
#define DIN  4
#define TT   25
#define HIDD 64
#define TPB  128          // 4 warps
#define COLS 32           // sample columns (float2 -> 64 samples/CTA)
#define SPC  64           // samples per CTA
#define TILES 512         // 32768 / 64
#define GRID (TILES*NBK)  // 2560
#define JW   8            // j rows per warp
#define JB   4            // j per pass (2 passes)

typedef unsigned long long u64;

// Weights interleaved [k][j][(i,f,g,o)]: one LDS.128 broadcast = 4 gate weights.
// State [k][col] float2 = (sample c, sample c+32): conflict-free, column-private.
struct SmemLayout {
    float Wp0p[DIN][HD][4];   //  2048 B
    float Wh0p[HD][HD][4];    // 16384 B
    float Wp1p[HD][HD][4];    // 16384 B
    float Wh1p[HD][HD][4];    // 16384 B
    float bp0[HD][4];         //   512 B
    float bp1[HD][4];         //   512 B
    float2 h0s[HD][COLS];     //  8192 B
    float2 h1s[HD][COLS];     //  8192 B
};                            // 68608 B -> 3 CTAs/SM (12 warps)

// MLP overlay offsets (floats) into the weight region (reused after recurrence)
#define OV_W1 0
#define OV_B1 2048
#define OV_W2 2112
#define OV_B2 6208

__device__ __forceinline__ u64 pk2(float v) {
    u64 r; asm("mov.b64 %0, {%1, %1};" : "=l"(r) : "f"(v)); return r;
}
__device__ __forceinline__ u64 f2fma(u64 a, u64 b, u64 c) {
    u64 d; asm("fma.rn.f32x2 %0, %1, %2, %3;" : "=l"(d) : "l"(a), "l"(b), "l"(c));
    return d;
}
__device__ __forceinline__ void unpk(u64 v, float& lo, float& hi) {
    asm("mov.b64 {%0, %1}, %2;" : "=f"(lo), "=f"(hi) : "l"(v));
}
__device__ __forceinline__ float sigf(float v) {
    return __fdividef(1.0f, 1.0f + __expf(-v));
}
__device__ __forceinline__ float tanhr(float v) {
    return __fdividef(2.0f, 1.0f + __expf(-2.0f * v)) - 1.0f;
}

__global__ void __launch_bounds__(TPB, 3) lstm_fused(
    const float* __restrict__ x,    const float* __restrict__ mask,
    const float* __restrict__ Wih0, const float* __restrict__ Whh0,
    const float* __restrict__ bih0, const float* __restrict__ bhh0,
    const float* __restrict__ Wih1, const float* __restrict__ Whh1,
    const float* __restrict__ bih1, const float* __restrict__ bhh1,
    const float* __restrict__ W1,   const float* __restrict__ b1,
    const float* __restrict__ W2,   const float* __restrict__ b2,
    float* __restrict__ out)
{
    extern __shared__ float smraw[];
    SmemLayout* S = reinterpret_cast<SmemLayout*>(smraw);
    const int tid   = threadIdx.x;
    const int lane  = tid & 31;          // sample column
    const int jbase = (tid >> 5) * JW;   // warp's j rows
    const int ib    = 4 - (blockIdx.x >> 9);        // heavy blocks first
    const int tile  = blockIdx.x & (TILES - 1);
    const int bA    = tile * SPC + lane;
    const int bB    = bA + COLS;

    // ---- stage weights into SMEM (interleaved) ----
    {
        const float* wih0 = Wih0 + ib * 4 * HD * DIN;
        for (int idx = tid; idx < 4 * HD * DIN; idx += TPB) {
            int r = idx / DIN, k = idx % DIN, g = r >> 5, j = r & 31;
            S->Wp0p[k][j][g] = wih0[idx];
        }
        const float* whh0 = Whh0 + ib * 4 * HD * HD;
        const float* wih1 = Wih1 + ib * 4 * HD * HD;
        const float* whh1 = Whh1 + ib * 4 * HD * HD;
        for (int idx = tid; idx < 4 * HD * HD; idx += TPB) {
            int r = idx / HD, k = idx % HD, g = r >> 5, j = r & 31;
            S->Wh0p[k][j][g] = whh0[idx];
            S->Wp1p[k][j][g] = wih1[idx];
            S->Wh1p[k][j][g] = whh1[idx];
        }
        for (int idx = tid; idx < 4 * HD; idx += TPB) {
            int g = idx >> 5, j = idx & 31;
            S->bp0[j][g] = bih0[ib * 4 * HD + idx] + bhh0[ib * 4 * HD + idx];
            S->bp1[j][g] = bih1[ib * 4 * HD + idx] + bhh1[ib * 4 * HD + idx];
        }
        float2* st = reinterpret_cast<float2*>(&S->h0s[0][0]);
        for (int i = tid; i < 2 * HD * COLS; i += TPB) st[i] = make_float2(0.0f, 0.0f);
    }
    __syncthreads();

    float2 c0[JW], c1[JW], hn[JW];
#pragma unroll
    for (int q = 0; q < JW; q++) {
        c0[q] = make_float2(0.0f, 0.0f);
        c1[q] = make_float2(0.0f, 0.0f);
    }

    const int Ti = 5 * (ib + 1);
    const float4* xpa = reinterpret_cast<const float4*>(x)    + (size_t)bA * TT + (TT - Ti);
    const float4* mpa = reinterpret_cast<const float4*>(mask) + (size_t)bA * TT + (TT - Ti);
    const float4* xpb = reinterpret_cast<const float4*>(x)    + (size_t)bB * TT + (TT - Ti);
    const float4* mpb = reinterpret_cast<const float4*>(mask) + (size_t)bB * TT + (TT - Ti);
    float4 xva = __ldg(xpa), mva = __ldg(mpa);
    float4 xvb = __ldg(xpb), mvb = __ldg(mpb);

    for (int s = 0; s < Ti; s++) {
        u64 xma2[DIN], xmb2[DIN];
        xma2[0] = pk2(xva.x * mva.x); xma2[1] = pk2(xva.y * mva.y);
        xma2[2] = pk2(xva.z * mva.z); xma2[3] = pk2(xva.w * mva.w);
        xmb2[0] = pk2(xvb.x * mvb.x); xmb2[1] = pk2(xvb.y * mvb.y);
        xmb2[2] = pk2(xvb.z * mvb.z); xmb2[3] = pk2(xvb.w * mvb.w);
        if (s + 1 < Ti) {
            xva = __ldg(xpa + s + 1); mva = __ldg(mpa + s + 1);
            xvb = __ldg(xpb + s + 1); mvb = __ldg(mpb + s + 1);
        }

        // ================= layer 0 compute (reads h0s old) =================
#pragma unroll
        for (int p = 0; p < JW / JB; p++) {
            u64 iA[JB], gA[JB], iB[JB], gB[JB];
#pragma unroll
            for (int q = 0; q < JB; q++) {
                ulonglong2 bb = *reinterpret_cast<const ulonglong2*>(S->bp0[jbase + p * JB + q]);
                iA[q] = bb.x; gA[q] = bb.y; iB[q] = bb.x; gB[q] = bb.y;
            }
#pragma unroll
            for (int k = 0; k < DIN; k++) {
#pragma unroll
                for (int q = 0; q < JB; q++) {
                    ulonglong2 w = *reinterpret_cast<const ulonglong2*>(S->Wp0p[k][jbase + p * JB + q]);
                    iA[q] = f2fma(w.x, xma2[k], iA[q]); gA[q] = f2fma(w.y, xma2[k], gA[q]);
                    iB[q] = f2fma(w.x, xmb2[k], iB[q]); gB[q] = f2fma(w.y, xmb2[k], gB[q]);
                }
            }
#pragma unroll 8
            for (int k = 0; k < HD; k++) {
                float2 hv = S->h0s[k][lane];
                u64 ha = pk2(hv.x), hb = pk2(hv.y);
#pragma unroll
                for (int q = 0; q < JB; q++) {
                    ulonglong2 w = *reinterpret_cast<const ulonglong2*>(S->Wh0p[k][jbase + p * JB + q]);
                    iA[q] = f2fma(w.x, ha, iA[q]); gA[q] = f2fma(w.y, ha, gA[q]);
                    iB[q] = f2fma(w.x, hb, iB[q]); gB[q] = f2fma(w.y, hb, gB[q]);
                }
            }
#pragma unroll
            for (int q = 0; q < JB; q++) {
                const int idx = p * JB + q;
                float ai, af, ag, ao, bi, bf, bg, bo;
                unpk(iA[q], ai, af); unpk(gA[q], ag, ao);
                unpk(iB[q], bi, bf); unpk(gB[q], bg, bo);
                float ca = sigf(af) * c0[idx].x + sigf(ai) * tanhr(ag);
                float cb = sigf(bf) * c0[idx].y + sigf(bi) * tanhr(bg);
                c0[idx] = make_float2(ca, cb);
                hn[idx] = make_float2(sigf(ao) * tanhr(ca), sigf(bo) * tanhr(cb));
            }
        }
        __syncthreads();   // all layer-0 reads of old h0s complete
#pragma unroll
        for (int q = 0; q < JW; q++) S->h0s[jbase + q][lane] = hn[q];
        __syncthreads();   // new h0s visible

        // ================= layer 1 compute (reads h0s new + h1s old) =================
#pragma unroll
        for (int p = 0; p < JW / JB; p++) {
            u64 iA[JB], gA[JB], iB[JB], gB[JB];
#pragma unroll
            for (int q = 0; q < JB; q++) {
                ulonglong2 bb = *reinterpret_cast<const ulonglong2*>(S->bp1[jbase + p * JB + q]);
                iA[q] = bb.x; gA[q] = bb.y; iB[q] = bb.x; gB[q] = bb.y;
            }
#pragma unroll 8
            for (int k = 0; k < HD; k++) {
                float2 hv = S->h0s[k][lane];
                u64 ha = pk2(hv.x), hb = pk2(hv.y);
#pragma unroll
                for (int q = 0; q < JB; q++) {
                    ulonglong2 w = *reinterpret_cast<const ulonglong2*>(S->Wp1p[k][jbase + p * JB + q]);
                    iA[q] = f2fma(w.x, ha, iA[q]); gA[q] = f2fma(w.y, ha, gA[q]);
                    iB[q] = f2fma(w.x, hb, iB[q]); gB[q] = f2fma(w.y, hb, gB[q]);
                }
            }
#pragma unroll 8
            for (int k = 0; k < HD; k++) {
                float2 hv = S->h1s[k][lane];
                u64 ha = pk2(hv.x), hb = pk2(hv.y);
#pragma unroll
                for (int q = 0; q < JB; q++) {
                    ulonglong2 w = *reinterpret_cast<const ulonglong2*>(S->Wh1p[k][jbase + p * JB + q]);
                    iA[q] = f2fma(w.x, ha, iA[q]); gA[q] = f2fma(w.y, ha, gA[q]);
                    iB[q] = f2fma(w.x, hb, iB[q]); gB[q] = f2fma(w.y, hb, gB[q]);
                }
            }
#pragma unroll
            for (int q = 0; q < JB; q++) {
                const int idx = p * JB + q;
                float ai, af, ag, ao, bi, bf, bg, bo;
                unpk(iA[q], ai, af); unpk(gA[q], ag, ao);
                unpk(iB[q], bi, bf); unpk(gB[q], bg, bo);
                float ca = sigf(af) * c1[idx].x + sigf(ai) * tanhr(ag);
                float cb = sigf(bf) * c1[idx].y + sigf(bi) * tanhr(bg);
                c1[idx] = make_float2(ca, cb);
                hn[idx] = make_float2(sigf(ao) * tanhr(ca), sigf(bo) * tanhr(cb));
            }
        }
        __syncthreads();   // all layer-1 reads of old h1s complete
#pragma unroll
        for (int q = 0; q < JW; q++) S->h1s[jbase + q][lane] = hn[q];
        // next-step ordering provided by next iteration's barriers
    }

    // ---- MLP head ----
    __syncthreads();   // h1s final visible; weight region about to be reused
    float* ov = smraw;
    for (int idx = tid; idx < HIDD * HD; idx += TPB)   ov[OV_W1 + idx] = W1[idx];
    for (int idx = tid; idx < HIDD * HIDD; idx += TPB) {
        int n = idx / HIDD, m = idx % HIDD;
        ov[OV_W2 + m * HIDD + n] = W2[idx];            // transposed [m][n]
    }
    if (tid < HIDD) { ov[OV_B1 + tid] = b1[tid]; ov[OV_B2 + tid] = b2[tid]; }
    __syncthreads();

    // 2 threads per sample: sidx = tid & 63 (sample), half = tid >> 6 (which 32 outputs)
    const int sidx = tid & 63;
    const int half = tid >> 6;
    const int scol = sidx & 31;
    const int shi  = sidx >> 5;

    float hr[HD];
#pragma unroll
    for (int k = 0; k < HD; k++) {
        float2 v = S->h1s[k][scol];
        hr[k] = shi ? v.y : v.x;
    }

    float acc2[HIDD / 2];
#pragma unroll
    for (int n = 0; n < HIDD / 2; n++) acc2[n] = ov[OV_B2 + half * (HIDD / 2) + n];

    for (int m = 0; m < HIDD; m++) {
        float tm = ov[OV_B1 + m];
        const float4* w1r = reinterpret_cast<const float4*>(&ov[OV_W1 + m * HD]);
#pragma unroll
        for (int q = 0; q < HD / 4; q++) {
            float4 w = w1r[q];
            tm += hr[4 * q + 0] * w.x + hr[4 * q + 1] * w.y
                + hr[4 * q + 2] * w.z + hr[4 * q + 3] * w.w;
        }
        tm = 0.5f * tm * (1.0f + erff(tm * 0.70710678118654752f));
        const float4* w2r = reinterpret_cast<const float4*>(
            &ov[OV_W2 + m * HIDD + half * (HIDD / 2)]);
#pragma unroll
        for (int q = 0; q < HIDD / 8; q++) {
            float4 w = w2r[q];
            acc2[4 * q + 0] += tm * w.x; acc2[4 * q + 1] += tm * w.y;
            acc2[4 * q + 2] += tm * w.z; acc2[4 * q + 3] += tm * w.w;
        }
    }

    const int bS = tile * SPC + sidx;
    float4* op = reinterpret_cast<float4*>(
        out + ((size_t)bS * NBK + ib) * HIDD + half * (HIDD / 2));
#pragma unroll
    for (int q = 0; q < HIDD / 8; q++)
        op[q] = make_float4(acc2[4 * q], acc2[4 * q + 1],
                            acc2[4 * q + 2], acc2[4 * q + 3]);
}

extern "C" void kernel_launch(void* const* d_in, const int* in_sizes, int n_in,
                              void* d_out, int out_size)
{
    const float* x    = (const float*)d_in[0];
    const float* mask = (const float*)d_in[1];
    const float* Wih0 = (const float*)d_in[2];
    const float* Whh0 = (const float*)d_in[3];
    const float* bih0 = (const float*)d_in[4];
    const float* bhh0 = (const float*)d_in[5];
    const float* Wih1 = (const float*)d_in[6];
    const float* Whh1 = (const float*)d_in[7];
    const float* bih1 = (const float*)d_in[8];
    const float* bhh1 = (const float*)d_in[9];
    const float* W1   = (const float*)d_in[10];
    const float* b1   = (const float*)d_in[11];
    const float* W2   = (const float*)d_in[12];
    const float* b2   = (const float*)d_in[13];
    float* out = (float*)d_out;

    const size_t smem = sizeof(SmemLayout);   // 68608 B -> 3 CTAs/SM
    cudaFuncSetAttribute(lstm_fused, cudaFuncAttributeMaxDynamicSharedMemorySize,
                         (int)smem);
    lstm_fused<<<GRID, TPB, smem>>>(x, mask, Wih0, Whh0, bih0, bhh0,
                                    Wih1, Whh1, bih1, bhh1, W1, b1, W2, b2, out);
}

// round 6
// speedup vs baseline: 3.3419x; 1.1372x over previous
#include <cuda_runtime.h>
#include <math.h>

#define NBK  5
#define HD   32
#define DIN  4
#define TT   25
#define HIDD 64
#define TPB  128          // 4 warps
#define COLS 32           // lanes = sample columns
#define SPT  4            // samples per thread (float4-packed)
#define SPC  128          // samples per CTA
#define TILES 256         // 32768 / 128
#define GRID (TILES*NBK)  // 1280
#define JW   8            // j rows per warp
#define JB   4            // j per pass (2 passes)

typedef unsigned long long u64;

// Weights interleaved [k][j][(i,f,g,o)]: one LDS.128 broadcast = 4 gate weights,
// reused by 4 samples (8 FFMA2 per weight load).
// State [k][col] float4 = samples (c, c+32, c+64, c+96): conflict-free, column-private.
struct SmemLayout {
    float Wp0p[DIN][HD][4];   //  2048 B
    float Wh0p[HD][HD][4];    // 16384 B
    float Wp1p[HD][HD][4];    // 16384 B
    float Wh1p[HD][HD][4];    // 16384 B
    float bp0[HD][4];         //   512 B
    float bp1[HD][4];         //   512 B
    float4 h0s[HD][COLS];     // 16384 B
    float4 h1s[HD][COLS];     // 16384 B
};                            // 84992 B -> 2 CTAs/SM (8 warps)

// MLP overlay offsets (floats) into the weight region (reused after recurrence)
#define OV_W1 0
#define OV_B1 2048
#define OV_W2 2112
#define OV_B2 6208

__device__ __forceinline__ u64 pk2(float v) {
    u64 r; asm("mov.b64 %0, {%1, %1};" : "=l"(r) : "f"(v)); return r;
}
__device__ __forceinline__ u64 f2fma(u64 a, u64 b, u64 c) {
    u64 d; asm("fma.rn.f32x2 %0, %1, %2, %3;" : "=l"(d) : "l"(a), "l"(b), "l"(c));
    return d;
}
__device__ __forceinline__ void unpk(u64 v, float& lo, float& hi) {
    asm("mov.b64 {%0, %1}, %2;" : "=f"(lo), "=f"(hi) : "l"(v));
}
__device__ __forceinline__ float sigf(float v) {
    return __fdividef(1.0f, 1.0f + __expf(-v));
}
__device__ __forceinline__ float tanhr(float v) {
    return __fdividef(2.0f, 1.0f + __expf(-2.0f * v)) - 1.0f;
}

__global__ void __launch_bounds__(TPB, 2) lstm_fused(
    const float* __restrict__ x,    const float* __restrict__ mask,
    const float* __restrict__ Wih0, const float* __restrict__ Whh0,
    const float* __restrict__ bih0, const float* __restrict__ bhh0,
    const float* __restrict__ Wih1, const float* __restrict__ Whh1,
    const float* __restrict__ bih1, const float* __restrict__ bhh1,
    const float* __restrict__ W1,   const float* __restrict__ b1,
    const float* __restrict__ W2,   const float* __restrict__ b2,
    float* __restrict__ out)
{
    extern __shared__ float smraw[];
    SmemLayout* S = reinterpret_cast<SmemLayout*>(smraw);
    const int tid   = threadIdx.x;
    const int lane  = tid & 31;          // sample column
    const int jbase = (tid >> 5) * JW;   // warp's j rows
    const int ib    = 4 - (blockIdx.x >> 8);        // heavy blocks first
    const int tile  = blockIdx.x & (TILES - 1);

    // ---- stage weights into SMEM (interleaved) ----
    {
        const float* wih0 = Wih0 + ib * 4 * HD * DIN;
        for (int idx = tid; idx < 4 * HD * DIN; idx += TPB) {
            int r = idx / DIN, k = idx % DIN, g = r >> 5, j = r & 31;
            S->Wp0p[k][j][g] = wih0[idx];
        }
        const float* whh0 = Whh0 + ib * 4 * HD * HD;
        const float* wih1 = Wih1 + ib * 4 * HD * HD;
        const float* whh1 = Whh1 + ib * 4 * HD * HD;
        for (int idx = tid; idx < 4 * HD * HD; idx += TPB) {
            int r = idx / HD, k = idx % HD, g = r >> 5, j = r & 31;
            S->Wh0p[k][j][g] = whh0[idx];
            S->Wp1p[k][j][g] = wih1[idx];
            S->Wh1p[k][j][g] = whh1[idx];
        }
        for (int idx = tid; idx < 4 * HD; idx += TPB) {
            int g = idx >> 5, j = idx & 31;
            S->bp0[j][g] = bih0[ib * 4 * HD + idx] + bhh0[ib * 4 * HD + idx];
            S->bp1[j][g] = bih1[ib * 4 * HD + idx] + bhh1[ib * 4 * HD + idx];
        }
        float4* st = reinterpret_cast<float4*>(&S->h0s[0][0]);
        for (int i = tid; i < 2 * HD * COLS; i += TPB)
            st[i] = make_float4(0.0f, 0.0f, 0.0f, 0.0f);
    }
    __syncthreads();

    float c0r[JW][SPT], c1r[JW][SPT], hnr[JW][SPT];
#pragma unroll
    for (int q = 0; q < JW; q++)
#pragma unroll
        for (int s4 = 0; s4 < SPT; s4++) { c0r[q][s4] = 0.0f; c1r[q][s4] = 0.0f; }

    const int Ti = 5 * (ib + 1);
    const float4* xp[SPT]; const float4* mp[SPT];
    float4 xv[SPT], mv[SPT];
#pragma unroll
    for (int s4 = 0; s4 < SPT; s4++) {
        const int b = tile * SPC + lane + s4 * COLS;
        xp[s4] = reinterpret_cast<const float4*>(x)    + (size_t)b * TT + (TT - Ti);
        mp[s4] = reinterpret_cast<const float4*>(mask) + (size_t)b * TT + (TT - Ti);
        xv[s4] = __ldg(xp[s4]); mv[s4] = __ldg(mp[s4]);
    }

    for (int st = 0; st < Ti; st++) {
        float xmf[SPT][DIN];
#pragma unroll
        for (int s4 = 0; s4 < SPT; s4++) {
            xmf[s4][0] = xv[s4].x * mv[s4].x; xmf[s4][1] = xv[s4].y * mv[s4].y;
            xmf[s4][2] = xv[s4].z * mv[s4].z; xmf[s4][3] = xv[s4].w * mv[s4].w;
        }
        if (st + 1 < Ti) {
#pragma unroll
            for (int s4 = 0; s4 < SPT; s4++) {
                xv[s4] = __ldg(xp[s4] + st + 1); mv[s4] = __ldg(mp[s4] + st + 1);
            }
        }

        // ================= layer 0 (reads h0s old) =================
#pragma unroll
        for (int p = 0; p < JW / JB; p++) {
            u64 aI[SPT][JB], aG[SPT][JB];
#pragma unroll
            for (int q = 0; q < JB; q++) {
                ulonglong2 bb = *reinterpret_cast<const ulonglong2*>(S->bp0[jbase + p * JB + q]);
#pragma unroll
                for (int s4 = 0; s4 < SPT; s4++) { aI[s4][q] = bb.x; aG[s4][q] = bb.y; }
            }
#pragma unroll
            for (int k = 0; k < DIN; k++) {
                u64 hx[SPT];
#pragma unroll
                for (int s4 = 0; s4 < SPT; s4++) hx[s4] = pk2(xmf[s4][k]);
#pragma unroll
                for (int q = 0; q < JB; q++) {
                    ulonglong2 w = *reinterpret_cast<const ulonglong2*>(S->Wp0p[k][jbase + p * JB + q]);
#pragma unroll
                    for (int s4 = 0; s4 < SPT; s4++) {
                        aI[s4][q] = f2fma(w.x, hx[s4], aI[s4][q]);
                        aG[s4][q] = f2fma(w.y, hx[s4], aG[s4][q]);
                    }
                }
            }
#pragma unroll 8
            for (int k = 0; k < HD; k++) {
                float4 hv = S->h0s[k][lane];
                u64 hh[SPT];
                hh[0] = pk2(hv.x); hh[1] = pk2(hv.y); hh[2] = pk2(hv.z); hh[3] = pk2(hv.w);
#pragma unroll
                for (int q = 0; q < JB; q++) {
                    ulonglong2 w = *reinterpret_cast<const ulonglong2*>(S->Wh0p[k][jbase + p * JB + q]);
#pragma unroll
                    for (int s4 = 0; s4 < SPT; s4++) {
                        aI[s4][q] = f2fma(w.x, hh[s4], aI[s4][q]);
                        aG[s4][q] = f2fma(w.y, hh[s4], aG[s4][q]);
                    }
                }
            }
#pragma unroll
            for (int q = 0; q < JB; q++) {
                const int idx = p * JB + q;
#pragma unroll
                for (int s4 = 0; s4 < SPT; s4++) {
                    float ai, af, ag, ao;
                    unpk(aI[s4][q], ai, af); unpk(aG[s4][q], ag, ao);
                    float cc = sigf(af) * c0r[idx][s4] + sigf(ai) * tanhr(ag);
                    c0r[idx][s4] = cc;
                    hnr[idx][s4] = sigf(ao) * tanhr(cc);
                }
            }
        }
        __syncthreads();   // all layer-0 reads of old h0s complete
#pragma unroll
        for (int q = 0; q < JW; q++)
            S->h0s[jbase + q][lane] = make_float4(hnr[q][0], hnr[q][1], hnr[q][2], hnr[q][3]);
        __syncthreads();   // new h0s visible

        // ================= layer 1 (reads h0s new + h1s old) =================
#pragma unroll
        for (int p = 0; p < JW / JB; p++) {
            u64 aI[SPT][JB], aG[SPT][JB];
#pragma unroll
            for (int q = 0; q < JB; q++) {
                ulonglong2 bb = *reinterpret_cast<const ulonglong2*>(S->bp1[jbase + p * JB + q]);
#pragma unroll
                for (int s4 = 0; s4 < SPT; s4++) { aI[s4][q] = bb.x; aG[s4][q] = bb.y; }
            }
#pragma unroll 8
            for (int k = 0; k < HD; k++) {
                float4 hv = S->h0s[k][lane];
                u64 hh[SPT];
                hh[0] = pk2(hv.x); hh[1] = pk2(hv.y); hh[2] = pk2(hv.z); hh[3] = pk2(hv.w);
#pragma unroll
                for (int q = 0; q < JB; q++) {
                    ulonglong2 w = *reinterpret_cast<const ulonglong2*>(S->Wp1p[k][jbase + p * JB + q]);
#pragma unroll
                    for (int s4 = 0; s4 < SPT; s4++) {
                        aI[s4][q] = f2fma(w.x, hh[s4], aI[s4][q]);
                        aG[s4][q] = f2fma(w.y, hh[s4], aG[s4][q]);
                    }
                }
            }
#pragma unroll 8
            for (int k = 0; k < HD; k++) {
                float4 hv = S->h1s[k][lane];
                u64 hh[SPT];
                hh[0] = pk2(hv.x); hh[1] = pk2(hv.y); hh[2] = pk2(hv.z); hh[3] = pk2(hv.w);
#pragma unroll
                for (int q = 0; q < JB; q++) {
                    ulonglong2 w = *reinterpret_cast<const ulonglong2*>(S->Wh1p[k][jbase + p * JB + q]);
#pragma unroll
                    for (int s4 = 0; s4 < SPT; s4++) {
                        aI[s4][q] = f2fma(w.x, hh[s4], aI[s4][q]);
                        aG[s4][q] = f2fma(w.y, hh[s4], aG[s4][q]);
                    }
                }
            }
#pragma unroll
            for (int q = 0; q < JB; q++) {
                const int idx = p * JB + q;
#pragma unroll
                for (int s4 = 0; s4 < SPT; s4++) {
                    float ai, af, ag, ao;
                    unpk(aI[s4][q], ai, af); unpk(aG[s4][q], ag, ao);
                    float cc = sigf(af) * c1r[idx][s4] + sigf(ai) * tanhr(ag);
                    c1r[idx][s4] = cc;
                    hnr[idx][s4] = sigf(ao) * tanhr(cc);
                }
            }
        }
        __syncthreads();   // all layer-1 reads of old h1s complete
#pragma unroll
        for (int q = 0; q < JW; q++)
            S->h1s[jbase + q][lane] = make_float4(hnr[q][0], hnr[q][1], hnr[q][2], hnr[q][3]);
        // next-step ordering provided by next iteration's barriers
    }

    // ---- MLP head: 1 thread per sample ----
    __syncthreads();   // h1s final visible; weight region about to be reused
    float* ov = smraw;
    for (int idx = tid; idx < HIDD * HD; idx += TPB)   ov[OV_W1 + idx] = W1[idx];
    for (int idx = tid; idx < HIDD * HIDD; idx += TPB) {
        int n = idx / HIDD, m = idx % HIDD;
        ov[OV_W2 + m * HIDD + n] = W2[idx];            // transposed [m][n]
    }
    if (tid < HIDD) { ov[OV_B1 + tid] = b1[tid]; ov[OV_B2 + tid] = b2[tid]; }
    __syncthreads();

    const int scol = tid & 31;
    const int sq   = tid >> 5;       // which float4 component

    float hr[HD];
#pragma unroll
    for (int k = 0; k < HD; k++) {
        float4 v = S->h1s[k][scol];
        hr[k] = (sq == 0) ? v.x : (sq == 1) ? v.y : (sq == 2) ? v.z : v.w;
    }

    float acc2[HIDD];
#pragma unroll
    for (int n = 0; n < HIDD; n++) acc2[n] = ov[OV_B2 + n];

    for (int m = 0; m < HIDD; m++) {
        float tm = ov[OV_B1 + m];
        const float4* w1r = reinterpret_cast<const float4*>(&ov[OV_W1 + m * HD]);
#pragma unroll
        for (int q = 0; q < HD / 4; q++) {
            float4 w = w1r[q];
            tm += hr[4 * q + 0] * w.x + hr[4 * q + 1] * w.y
                + hr[4 * q + 2] * w.z + hr[4 * q + 3] * w.w;
        }
        tm = 0.5f * tm * (1.0f + erff(tm * 0.70710678118654752f));
        const float4* w2r = reinterpret_cast<const float4*>(&ov[OV_W2 + m * HIDD]);
#pragma unroll
        for (int q = 0; q < HIDD / 4; q++) {
            float4 w = w2r[q];
            acc2[4 * q + 0] += tm * w.x; acc2[4 * q + 1] += tm * w.y;
            acc2[4 * q + 2] += tm * w.z; acc2[4 * q + 3] += tm * w.w;
        }
    }

    const int bS = tile * SPC + sq * COLS + scol;
    float4* op = reinterpret_cast<float4*>(out + ((size_t)bS * NBK + ib) * HIDD);
#pragma unroll
    for (int q = 0; q < HIDD / 4; q++)
        op[q] = make_float4(acc2[4 * q], acc2[4 * q + 1],
                            acc2[4 * q + 2], acc2[4 * q + 3]);
}

extern "C" void kernel_launch(void* const* d_in, const int* in_sizes, int n_in,
                              void* d_out, int out_size)
{
    const float* x    = (const float*)d_in[0];
    const float* mask = (const float*)d_in[1];
    const float* Wih0 = (const float*)d_in[2];
    const float* Whh0 = (const float*)d_in[3];
    const float* bih0 = (const float*)d_in[4];
    const float* bhh0 = (const float*)d_in[5];
    const float* Wih1 = (const float*)d_in[6];
    const float* Whh1 = (const float*)d_in[7];
    const float* bih1 = (const float*)d_in[8];
    const float* bhh1 = (const float*)d_in[9];
    const float* W1   = (const float*)d_in[10];
    const float* b1   = (const float*)d_in[11];
    const float* W2   = (const float*)d_in[12];
    const float* b2   = (const float*)d_in[13];
    float* out = (float*)d_out;

    const size_t smem = sizeof(SmemLayout);   // 84992 B -> 2 CTAs/SM
    cudaFuncSetAttribute(lstm_fused, cudaFuncAttributeMaxDynamicSharedMemorySize,
                         (int)smem);
    lstm_fused<<<GRID, TPB, smem>>>(x, mask, Wih0, Whh0, bih0, bhh0,
                                    Wih1, Whh1, bih1, bhh1, W1, b1, W2, b2, out);
}

// round 7
// speedup vs baseline: 3.6094x; 1.0800x over previous
#include <cuda_runtime.h>
#include <math.h>

#define NBK  5
#define HD   32
#define DIN  4
#define TT   25
#define HIDD 64
#define TPB  128          // 4 warps
#define COLS 32           // lanes = sample columns
#define SPT  4            // samples per thread (float4-packed)
#define SPC  128          // samples per CTA
#define TILES 256         // 32768 / 128
#define GRID (TILES*NBK)  // 1280
#define JW   8            // j rows per warp
#define JB   4            // j per pass (2 passes)

typedef unsigned long long u64;

// Weights interleaved [k][j][(i,f,g,o)]: one LDS.128 broadcast = 4 gate weights,
// reused by 4 samples (8 FFMA2 per weight load).
// State [k][col] float4 = samples (c, c+32, c+64, c+96): conflict-free, column-private.
// h0s is double-buffered (parity by step) -> only 2 barriers per step.
struct SmemLayout {
    float Wp0p[DIN][HD][4];   //  2048 B
    float Wh0p[HD][HD][4];    // 16384 B
    float Wp1p[HD][HD][4];    // 16384 B
    float Wh1p[HD][HD][4];    // 16384 B
    float bp0[HD][4];         //   512 B
    float bp1[HD][4];         //   512 B
    float4 h0s[2][HD][COLS];  // 32768 B (double-buffered)
    float4 h1s[HD][COLS];     // 16384 B
};                            // 101376 B -> 2 CTAs/SM (8 warps)

// MLP overlay offsets (floats) into the weight region (reused after recurrence)
#define OV_W1 0
#define OV_B1 2048
#define OV_W2 2112
#define OV_B2 6208

__device__ __forceinline__ u64 pk2(float v) {
    u64 r; asm("mov.b64 %0, {%1, %1};" : "=l"(r) : "f"(v)); return r;
}
__device__ __forceinline__ u64 f2fma(u64 a, u64 b, u64 c) {
    u64 d; asm("fma.rn.f32x2 %0, %1, %2, %3;" : "=l"(d) : "l"(a), "l"(b), "l"(c));
    return d;
}
__device__ __forceinline__ void unpk(u64 v, float& lo, float& hi) {
    asm("mov.b64 {%0, %1}, %2;" : "=f"(lo), "=f"(hi) : "l"(v));
}
// HW tanh (MUFU.TANH): 1 op vs exp+rcp chains
__device__ __forceinline__ float tanhfast(float x) {
    float y; asm("tanh.approx.f32 %0, %1;" : "=f"(y) : "f"(x)); return y;
}
// sigmoid(x) = 0.5*tanh(x/2) + 0.5  -> 1 MUFU + 1 mul + 1 fma
__device__ __forceinline__ float sigf(float v) {
    return fmaf(0.5f, tanhfast(0.5f * v), 0.5f);
}

__global__ void __launch_bounds__(TPB, 2) lstm_fused(
    const float* __restrict__ x,    const float* __restrict__ mask,
    const float* __restrict__ Wih0, const float* __restrict__ Whh0,
    const float* __restrict__ bih0, const float* __restrict__ bhh0,
    const float* __restrict__ Wih1, const float* __restrict__ Whh1,
    const float* __restrict__ bih1, const float* __restrict__ bhh1,
    const float* __restrict__ W1,   const float* __restrict__ b1,
    const float* __restrict__ W2,   const float* __restrict__ b2,
    float* __restrict__ out)
{
    extern __shared__ float smraw[];
    SmemLayout* S = reinterpret_cast<SmemLayout*>(smraw);
    const int tid   = threadIdx.x;
    const int lane  = tid & 31;          // sample column
    const int jbase = (tid >> 5) * JW;   // warp's j rows
    const int ib    = 4 - (blockIdx.x >> 8);        // heavy blocks first
    const int tile  = blockIdx.x & (TILES - 1);

    // ---- stage weights into SMEM (interleaved) ----
    {
        const float* wih0 = Wih0 + ib * 4 * HD * DIN;
        for (int idx = tid; idx < 4 * HD * DIN; idx += TPB) {
            int r = idx / DIN, k = idx % DIN, g = r >> 5, j = r & 31;
            S->Wp0p[k][j][g] = wih0[idx];
        }
        const float* whh0 = Whh0 + ib * 4 * HD * HD;
        const float* wih1 = Wih1 + ib * 4 * HD * HD;
        const float* whh1 = Whh1 + ib * 4 * HD * HD;
        for (int idx = tid; idx < 4 * HD * HD; idx += TPB) {
            int r = idx / HD, k = idx % HD, g = r >> 5, j = r & 31;
            S->Wh0p[k][j][g] = whh0[idx];
            S->Wp1p[k][j][g] = wih1[idx];
            S->Wh1p[k][j][g] = whh1[idx];
        }
        for (int idx = tid; idx < 4 * HD; idx += TPB) {
            int g = idx >> 5, j = idx & 31;
            S->bp0[j][g] = bih0[ib * 4 * HD + idx] + bhh0[ib * 4 * HD + idx];
            S->bp1[j][g] = bih1[ib * 4 * HD + idx] + bhh1[ib * 4 * HD + idx];
        }
        // zero h0s[0] and h1s (h0s[1] is write-before-read)
        float4* st0 = reinterpret_cast<float4*>(&S->h0s[0][0][0]);
        for (int i = tid; i < HD * COLS; i += TPB) st0[i] = make_float4(0.f, 0.f, 0.f, 0.f);
        float4* st1 = reinterpret_cast<float4*>(&S->h1s[0][0]);
        for (int i = tid; i < HD * COLS; i += TPB) st1[i] = make_float4(0.f, 0.f, 0.f, 0.f);
    }
    __syncthreads();

    float c0r[JW][SPT], c1r[JW][SPT], hnr[JW][SPT];
#pragma unroll
    for (int q = 0; q < JW; q++)
#pragma unroll
        for (int s4 = 0; s4 < SPT; s4++) { c0r[q][s4] = 0.0f; c1r[q][s4] = 0.0f; }

    const int Ti = 5 * (ib + 1);
    const float4* xp[SPT]; const float4* mp[SPT];
    float4 xv[SPT], mv[SPT];
#pragma unroll
    for (int s4 = 0; s4 < SPT; s4++) {
        const int b = tile * SPC + lane + s4 * COLS;
        xp[s4] = reinterpret_cast<const float4*>(x)    + (size_t)b * TT + (TT - Ti);
        mp[s4] = reinterpret_cast<const float4*>(mask) + (size_t)b * TT + (TT - Ti);
        xv[s4] = __ldg(xp[s4]); mv[s4] = __ldg(mp[s4]);
    }

    for (int st = 0; st < Ti; st++) {
        const int rb = st & 1, wb = 1 - rb;     // h0 double-buffer parity
        float xmf[SPT][DIN];
#pragma unroll
        for (int s4 = 0; s4 < SPT; s4++) {
            xmf[s4][0] = xv[s4].x * mv[s4].x; xmf[s4][1] = xv[s4].y * mv[s4].y;
            xmf[s4][2] = xv[s4].z * mv[s4].z; xmf[s4][3] = xv[s4].w * mv[s4].w;
        }
        if (st + 1 < Ti) {
#pragma unroll
            for (int s4 = 0; s4 < SPT; s4++) {
                xv[s4] = __ldg(xp[s4] + st + 1); mv[s4] = __ldg(mp[s4] + st + 1);
            }
        }

        // ================= layer 0 (reads h0s[rb]) =================
#pragma unroll
        for (int p = 0; p < JW / JB; p++) {
            u64 aI[SPT][JB], aG[SPT][JB];
#pragma unroll
            for (int q = 0; q < JB; q++) {
                ulonglong2 bb = *reinterpret_cast<const ulonglong2*>(S->bp0[jbase + p * JB + q]);
#pragma unroll
                for (int s4 = 0; s4 < SPT; s4++) { aI[s4][q] = bb.x; aG[s4][q] = bb.y; }
            }
#pragma unroll
            for (int k = 0; k < DIN; k++) {
                u64 hx[SPT];
#pragma unroll
                for (int s4 = 0; s4 < SPT; s4++) hx[s4] = pk2(xmf[s4][k]);
#pragma unroll
                for (int q = 0; q < JB; q++) {
                    ulonglong2 w = *reinterpret_cast<const ulonglong2*>(S->Wp0p[k][jbase + p * JB + q]);
#pragma unroll
                    for (int s4 = 0; s4 < SPT; s4++) {
                        aI[s4][q] = f2fma(w.x, hx[s4], aI[s4][q]);
                        aG[s4][q] = f2fma(w.y, hx[s4], aG[s4][q]);
                    }
                }
            }
#pragma unroll 8
            for (int k = 0; k < HD; k++) {
                float4 hv = S->h0s[rb][k][lane];
                u64 hh[SPT];
                hh[0] = pk2(hv.x); hh[1] = pk2(hv.y); hh[2] = pk2(hv.z); hh[3] = pk2(hv.w);
#pragma unroll
                for (int q = 0; q < JB; q++) {
                    ulonglong2 w = *reinterpret_cast<const ulonglong2*>(S->Wh0p[k][jbase + p * JB + q]);
#pragma unroll
                    for (int s4 = 0; s4 < SPT; s4++) {
                        aI[s4][q] = f2fma(w.x, hh[s4], aI[s4][q]);
                        aG[s4][q] = f2fma(w.y, hh[s4], aG[s4][q]);
                    }
                }
            }
#pragma unroll
            for (int q = 0; q < JB; q++) {
                const int idx = p * JB + q;
#pragma unroll
                for (int s4 = 0; s4 < SPT; s4++) {
                    float ai, af, ag, ao;
                    unpk(aI[s4][q], ai, af); unpk(aG[s4][q], ag, ao);
                    float cc = sigf(af) * c0r[idx][s4] + sigf(ai) * tanhfast(ag);
                    c0r[idx][s4] = cc;
                    hnr[idx][s4] = sigf(ao) * tanhfast(cc);
                }
            }
        }
        // write new h0 to the OTHER buffer: no barrier needed before writes
#pragma unroll
        for (int q = 0; q < JW; q++)
            S->h0s[wb][jbase + q][lane] = make_float4(hnr[q][0], hnr[q][1], hnr[q][2], hnr[q][3]);
        __syncthreads();   // new h0 visible; also orders prev-step h1 writes for L1 below

        // ================= layer 1 (reads h0s[wb] new + h1s old) =================
#pragma unroll
        for (int p = 0; p < JW / JB; p++) {
            u64 aI[SPT][JB], aG[SPT][JB];
#pragma unroll
            for (int q = 0; q < JB; q++) {
                ulonglong2 bb = *reinterpret_cast<const ulonglong2*>(S->bp1[jbase + p * JB + q]);
#pragma unroll
                for (int s4 = 0; s4 < SPT; s4++) { aI[s4][q] = bb.x; aG[s4][q] = bb.y; }
            }
#pragma unroll 8
            for (int k = 0; k < HD; k++) {
                float4 hv = S->h0s[wb][k][lane];
                u64 hh[SPT];
                hh[0] = pk2(hv.x); hh[1] = pk2(hv.y); hh[2] = pk2(hv.z); hh[3] = pk2(hv.w);
#pragma unroll
                for (int q = 0; q < JB; q++) {
                    ulonglong2 w = *reinterpret_cast<const ulonglong2*>(S->Wp1p[k][jbase + p * JB + q]);
#pragma unroll
                    for (int s4 = 0; s4 < SPT; s4++) {
                        aI[s4][q] = f2fma(w.x, hh[s4], aI[s4][q]);
                        aG[s4][q] = f2fma(w.y, hh[s4], aG[s4][q]);
                    }
                }
            }
#pragma unroll 8
            for (int k = 0; k < HD; k++) {
                float4 hv = S->h1s[k][lane];
                u64 hh[SPT];
                hh[0] = pk2(hv.x); hh[1] = pk2(hv.y); hh[2] = pk2(hv.z); hh[3] = pk2(hv.w);
#pragma unroll
                for (int q = 0; q < JB; q++) {
                    ulonglong2 w = *reinterpret_cast<const ulonglong2*>(S->Wh1p[k][jbase + p * JB + q]);
#pragma unroll
                    for (int s4 = 0; s4 < SPT; s4++) {
                        aI[s4][q] = f2fma(w.x, hh[s4], aI[s4][q]);
                        aG[s4][q] = f2fma(w.y, hh[s4], aG[s4][q]);
                    }
                }
            }
#pragma unroll
            for (int q = 0; q < JB; q++) {
                const int idx = p * JB + q;
#pragma unroll
                for (int s4 = 0; s4 < SPT; s4++) {
                    float ai, af, ag, ao;
                    unpk(aI[s4][q], ai, af); unpk(aG[s4][q], ag, ao);
                    float cc = sigf(af) * c1r[idx][s4] + sigf(ai) * tanhfast(ag);
                    c1r[idx][s4] = cc;
                    hnr[idx][s4] = sigf(ao) * tanhfast(cc);
                }
            }
        }
        __syncthreads();   // all layer-1 reads of old h1s complete
#pragma unroll
        for (int q = 0; q < JW; q++)
            S->h1s[jbase + q][lane] = make_float4(hnr[q][0], hnr[q][1], hnr[q][2], hnr[q][3]);
        // h1 writes are ordered for next step's L1 by the first barrier of next step
    }

    // ---- MLP head: 1 thread per sample ----
    __syncthreads();   // h1s final visible; weight region about to be reused
    float* ov = smraw;
    for (int idx = tid; idx < HIDD * HD; idx += TPB)   ov[OV_W1 + idx] = W1[idx];
    for (int idx = tid; idx < HIDD * HIDD; idx += TPB) {
        int n = idx / HIDD, m = idx % HIDD;
        ov[OV_W2 + m * HIDD + n] = W2[idx];            // transposed [m][n]
    }
    if (tid < HIDD) { ov[OV_B1 + tid] = b1[tid]; ov[OV_B2 + tid] = b2[tid]; }
    __syncthreads();

    const int scol = tid & 31;
    const int sq   = tid >> 5;       // which float4 component

    float hr[HD];
#pragma unroll
    for (int k = 0; k < HD; k++) {
        float4 v = S->h1s[k][scol];
        hr[k] = (sq == 0) ? v.x : (sq == 1) ? v.y : (sq == 2) ? v.z : v.w;
    }

    float acc2[HIDD];
#pragma unroll
    for (int n = 0; n < HIDD; n++) acc2[n] = ov[OV_B2 + n];

    for (int m = 0; m < HIDD; m++) {
        float tm = ov[OV_B1 + m];
        const float4* w1r = reinterpret_cast<const float4*>(&ov[OV_W1 + m * HD]);
#pragma unroll
        for (int q = 0; q < HD / 4; q++) {
            float4 w = w1r[q];
            tm += hr[4 * q + 0] * w.x + hr[4 * q + 1] * w.y
                + hr[4 * q + 2] * w.z + hr[4 * q + 3] * w.w;
        }
        // exact gelu (erf) -- output-level precision matters here
        tm = 0.5f * tm * (1.0f + erff(tm * 0.70710678118654752f));
        const float4* w2r = reinterpret_cast<const float4*>(&ov[OV_W2 + m * HIDD]);
#pragma unroll
        for (int q = 0; q < HIDD / 4; q++) {
            float4 w = w2r[q];
            acc2[4 * q + 0] += tm * w.x; acc2[4 * q + 1] += tm * w.y;
            acc2[4 * q + 2] += tm * w.z; acc2[4 * q + 3] += tm * w.w;
        }
    }

    const int bS = tile * SPC + sq * COLS + scol;
    float4* op = reinterpret_cast<float4*>(out + ((size_t)bS * NBK + ib) * HIDD);
#pragma unroll
    for (int q = 0; q < HIDD / 4; q++)
        op[q] = make_float4(acc2[4 * q], acc2[4 * q + 1],
                            acc2[4 * q + 2], acc2[4 * q + 3]);
}

extern "C" void kernel_launch(void* const* d_in, const int* in_sizes, int n_in,
                              void* d_out, int out_size)
{
    const float* x    = (const float*)d_in[0];
    const float* mask = (const float*)d_in[1];
    const float* Wih0 = (const float*)d_in[2];
    const float* Whh0 = (const float*)d_in[3];
    const float* bih0 = (const float*)d_in[4];
    const float* bhh0 = (const float*)d_in[5];
    const float* Wih1 = (const float*)d_in[6];
    const float* Whh1 = (const float*)d_in[7];
    const float* bih1 = (const float*)d_in[8];
    const float* bhh1 = (const float*)d_in[9];
    const float* W1   = (const float*)d_in[10];
    const float* b1   = (const float*)d_in[11];
    const float* W2   = (const float*)d_in[12];
    const float* b2   = (const float*)d_in[13];
    float* out = (float*)d_out;

    const size_t smem = sizeof(SmemLayout);   // 101376 B -> 2 CTAs/SM
    cudaFuncSetAttribute(lstm_fused, cudaFuncAttributeMaxDynamicSharedMemorySize,
                         (int)smem);
    lstm_fused<<<GRID, TPB, smem>>>(x, mask, Wih0, Whh0, bih0, bhh0,
                                    Wih1, Whh1, bih1, bhh1, W1, b1, W2, b2, out);
}